// round 11
// baseline (speedup 1.0000x reference)
#include <cuda_runtime.h>
#include <cuda_bf16.h>
#include <math.h>
#include <stdint.h>

// Problem constants
#define BWIN 256      // windows*batch
#define NTOK 256      // tokens per window
#define CDIM 384
#define NHEAD 12
#define HDIM 32
#define MROWS (BWIN*NTOK)   // 65536
#define TBL 961             // (2*16-1)^2
#define CPBH 512
#define LOG2E 1.44269504088896f

// ---------------- scratch (device globals; no allocs allowed) ----------------
__device__ float g_qkv[3ull * MROWS * CDIM];     // [3][M][384] f32
__device__ float g_attout[(size_t)MROWS * CDIM]; // [M][384] (tf32-rounded f32)
__device__ float g_xt[(size_t)MROWS * CDIM];     // x pre-rounded to tf32
__device__ float g_wt[3 * CDIM * CDIM];          // qkv_w pre-rounded
__device__ float g_pwt[CDIM * CDIM];             // proj_w pre-rounded
__device__ float g_bt[TBL * NHEAD];
__device__ float g_rpb[(size_t)NHEAD * NTOK * NTOK];

// ---------------- small helpers ----------------
__device__ __forceinline__ uint32_t f2tf(float f) {
    uint32_t u;
    asm("cvt.rna.tf32.f32 %0, %1;" : "=r"(u) : "f"(f));
    return u;
}
__device__ __forceinline__ float ex2(float x) {
    float r;
    asm("ex2.approx.ftz.f32 %0, %1;" : "=f"(r) : "f"(x));
    return r;
}
__device__ __forceinline__ uint32_t smem_u32(const void* p) {
    uint32_t a;
    asm("{ .reg .u64 t; cvta.to.shared.u64 t, %1; cvt.u32.u64 %0, t; }" : "=r"(a) : "l"(p));
    return a;
}
__device__ __forceinline__ void cp16(uint32_t s, const void* g) {
    asm volatile("cp.async.cg.shared.global [%0], [%1], 16;" :: "r"(s), "l"(g) : "memory");
}
__device__ __forceinline__ void ldsm_x4(uint32_t& r0, uint32_t& r1, uint32_t& r2,
                                        uint32_t& r3, uint32_t addr) {
    asm volatile("ldmatrix.sync.aligned.m8n8.x4.shared.b16 {%0,%1,%2,%3}, [%4];"
                 : "=r"(r0), "=r"(r1), "=r"(r2), "=r"(r3) : "r"(addr));
}
__device__ __forceinline__ void mma_tf32(float* c, const uint32_t* a, const uint32_t* b) {
    asm volatile(
        "mma.sync.aligned.m16n8k8.row.col.f32.tf32.tf32.f32 "
        "{%0,%1,%2,%3}, {%4,%5,%6,%7}, {%8,%9}, {%0,%1,%2,%3};\n"
        : "+f"(c[0]), "+f"(c[1]), "+f"(c[2]), "+f"(c[3])
        : "r"(a[0]), "r"(a[1]), "r"(a[2]), "r"(a[3]), "r"(b[0]), "r"(b[1]));
}
__device__ __forceinline__ void mma_bf16(float* c, const uint32_t* a, const uint32_t* b) {
    asm volatile(
        "mma.sync.aligned.m16n8k16.row.col.f32.bf16.bf16.f32 "
        "{%0,%1,%2,%3}, {%4,%5,%6,%7}, {%8,%9}, {%0,%1,%2,%3};\n"
        : "+f"(c[0]), "+f"(c[1]), "+f"(c[2]), "+f"(c[3])
        : "r"(a[0]), "r"(a[1]), "r"(a[2]), "r"(a[3]), "r"(b[0]), "r"(b[1]));
}
__device__ __forceinline__ void hilo_pack(float x, float y, uint32_t& wh, uint32_t& wl) {
    __nv_bfloat16 hx = __float2bfloat16(x);
    __nv_bfloat16 hy = __float2bfloat16(y);
    __nv_bfloat16 lx = __float2bfloat16(x - __bfloat162float(hx));
    __nv_bfloat16 ly = __float2bfloat16(y - __bfloat162float(hy));
    wh = (uint32_t)__bfloat16_as_ushort(hx) | ((uint32_t)__bfloat16_as_ushort(hy) << 16);
    wl = (uint32_t)__bfloat16_as_ushort(lx) | ((uint32_t)__bfloat16_as_ushort(ly) << 16);
}

// ---------------- conversion kernel: round f32 -> tf32 bit pattern ----------------
__global__ __launch_bounds__(256) void cvt_tf32_kernel(const float* __restrict__ in,
                                                       float* __restrict__ out, int n4) {
    int i = blockIdx.x * 256 + threadIdx.x;
    if (i >= n4) return;
    float4 v = ((const float4*)in)[i];
    v.x = __uint_as_float(f2tf(v.x));
    v.y = __uint_as_float(f2tf(v.y));
    v.z = __uint_as_float(f2tf(v.z));
    v.w = __uint_as_float(f2tf(v.w));
    ((float4*)out)[i] = v;
}

// ==================== tf32 mma.sync GEMM: K-chunk 32, 3-stage cp.async ====================
// C[m][n] = sum_k A[m][k]*B[n][k], K=384, operands pre-rounded tf32 in gmem.
// CTA tile 128x128, 256 thr = 8 warps (2m x 4n), warp tile m64 x n32, K-chunk 32.
// Stage rows stride 36 words (144 B = 9 x 16B slots, gcd(9,8)=1 -> ldmatrix conflict-free).
// Order per iter: [wait g<=1][syncthreads][cp c+2][ldsm+mma over 4 k-steps].
#define NSTG 3
#define STW 36
#define STG_A_WORDS (128 * STW)            // 4608 words
#define STG_A_BYTES (STG_A_WORDS * 4)      // 18432 B
#define STG_BYTES (2 * STG_A_BYTES)        // 36864 B (A + B)
#define GEMM_SMEM (NSTG * STG_BYTES)       // 110592 B
#define NCHUNK (CDIM / 32)                 // 12

#define CP_CHUNK(c_) do { \
    const int b_ = (c_) % NSTG; \
    const uint32_t ab_ = sb + b_ * STG_BYTES; \
    const uint32_t bb_ = ab_ + STG_A_BYTES; \
    const float* ga_ = Ag + (size_t)lrow * CDIM + (c_) * 32 + half * 16; \
    const float* gb_ = Bg + (size_t)lrow * CDIM + (c_) * 32 + half * 16; \
    const uint32_t so_ = lrow * (STW * 4) + half * 64; \
    cp16(ab_ + so_,      ga_);      cp16(ab_ + so_ + 16, ga_ + 4); \
    cp16(ab_ + so_ + 32, ga_ + 8);  cp16(ab_ + so_ + 48, ga_ + 12); \
    cp16(bb_ + so_,      gb_);      cp16(bb_ + so_ + 16, gb_ + 4); \
    cp16(bb_ + so_ + 32, gb_ + 8);  cp16(bb_ + so_ + 48, gb_ + 12); \
    asm volatile("cp.async.commit_group;" ::: "memory"); \
} while (0)

__device__ __forceinline__ void mma_gemm_core(
    const float* __restrict__ Ag, const float* __restrict__ Bg,
    float acc[4][4][4], char* smem) {
    const uint32_t sb = smem_u32(smem);
    const int tid = threadIdx.x;
    const int lane = tid & 31;
    const int wm = ((tid >> 5) >> 2) * 64;   // warp m offset (0,64)
    const int wn = ((tid >> 5) & 3) * 32;    // warp n offset (0..96)
    const int lrow = tid >> 1;               // 0..127
    const int half = tid & 1;                // 0..1

    // ldmatrix per-lane base offsets (words, within a stage)
    const int arow = (lane & 7) + (lane & 8);           // 0..15
    const int acol = (lane & 16) ? 4 : 0;
    const uint32_t aoffw = (uint32_t)((wm + arow) * STW + acol);
    const int brow = (lane & 7) + ((lane & 16) ? 8 : 0);
    const int bcol = (lane & 8) ? 4 : 0;
    const uint32_t boffw = (uint32_t)((wn + brow) * STW + bcol);

    CP_CHUNK(0); CP_CHUNK(1);

#pragma unroll 1
    for (int c = 0; c < NCHUNK; c++) {
        asm volatile("cp.async.wait_group 1;" ::: "memory");
        __syncthreads();
        if (c + 2 < NCHUNK) {
            CP_CHUNK(c + 2);
        } else {
            asm volatile("cp.async.commit_group;" ::: "memory");
        }

        const uint32_t abase = sb + (c % NSTG) * STG_BYTES;
        const uint32_t bbase = abase + STG_A_BYTES;
#pragma unroll
        for (int ks = 0; ks < 4; ks++) {
            uint32_t a[4][4], b[2][4];
#pragma unroll
            for (int mt = 0; mt < 4; mt++)
                ldsm_x4(a[mt][0], a[mt][1], a[mt][2], a[mt][3],
                        abase + ((aoffw + (uint32_t)(mt * 16 * STW + ks * 8)) << 2));
#pragma unroll
            for (int pr = 0; pr < 2; pr++)
                ldsm_x4(b[pr][0], b[pr][1], b[pr][2], b[pr][3],
                        bbase + ((boffw + (uint32_t)(pr * 16 * STW + ks * 8)) << 2));
#pragma unroll
            for (int mt = 0; mt < 4; mt++)
#pragma unroll
                for (int nt = 0; nt < 4; nt++)
                    mma_tf32(acc[mt][nt], a[mt], &b[nt >> 1][(nt & 1) * 2]);
        }
    }
}

// QKV: A=g_xt, B=g_wt, out -> g_qkv (+ q/v bias)
__global__ __launch_bounds__(256, 2) void qkv_mma_kernel(
    const float* __restrict__ qb, const float* __restrict__ vb) {
    extern __shared__ char smem[];
    float acc[4][4][4];
#pragma unroll
    for (int i = 0; i < 4; i++)
#pragma unroll
        for (int j = 0; j < 4; j++)
#pragma unroll
            for (int k = 0; k < 4; k++) acc[i][j][k] = 0.f;

    const float* Ag = g_xt + (size_t)blockIdx.y * 128 * CDIM;
    const float* Bg = g_wt + (size_t)blockIdx.x * 128 * CDIM;
    mma_gemm_core(Ag, Bg, acc, smem);

    const int tid = threadIdx.x;
    const int lane = tid & 31;
    const int wm = ((tid >> 5) >> 2) * 64;
    const int wn = ((tid >> 5) & 3) * 32;
    const int g = lane >> 2, tg = lane & 3;

    const int nbase = blockIdx.x * 128;
    const int which = nbase / CDIM;
    const int cb = nbase % CDIM;
    float* outp = g_qkv + (size_t)which * MROWS * CDIM;

#pragma unroll
    for (int mt = 0; mt < 4; mt++) {
        const int row = blockIdx.y * 128 + wm + mt * 16 + g;
#pragma unroll
        for (int nt = 0; nt < 4; nt++) {
            const int col = cb + wn + nt * 8 + 2 * tg;
            float b0 = 0.f, b1 = 0.f;
            if (which == 0) { b0 = qb[col]; b1 = qb[col + 1]; }
            else if (which == 2) { b0 = vb[col]; b1 = vb[col + 1]; }
            float2 o0 = make_float2(acc[mt][nt][0] + b0, acc[mt][nt][1] + b1);
            float2 o1 = make_float2(acc[mt][nt][2] + b0, acc[mt][nt][3] + b1);
            *(float2*)(outp + (size_t)row * CDIM + col) = o0;
            *(float2*)(outp + (size_t)(row + 8) * CDIM + col) = o1;
        }
    }
}

// Proj: A=g_attout (tf32-rounded by attention), B=g_pwt, out -> d_out (+ bias)
__global__ __launch_bounds__(256, 2) void proj_mma_kernel(
    const float* __restrict__ pb, float* __restrict__ out) {
    extern __shared__ char smem[];
    float acc[4][4][4];
#pragma unroll
    for (int i = 0; i < 4; i++)
#pragma unroll
        for (int j = 0; j < 4; j++)
#pragma unroll
            for (int k = 0; k < 4; k++) acc[i][j][k] = 0.f;

    const float* Ag = g_attout + (size_t)blockIdx.y * 128 * CDIM;
    const float* Bg = g_pwt + (size_t)blockIdx.x * 128 * CDIM;
    mma_gemm_core(Ag, Bg, acc, smem);

    const int tid = threadIdx.x;
    const int lane = tid & 31;
    const int wm = ((tid >> 5) >> 2) * 64;
    const int wn = ((tid >> 5) & 3) * 32;
    const int g = lane >> 2, tg = lane & 3;
    const int nbase = blockIdx.x * 128;

#pragma unroll
    for (int mt = 0; mt < 4; mt++) {
        const int row = blockIdx.y * 128 + wm + mt * 16 + g;
#pragma unroll
        for (int nt = 0; nt < 4; nt++) {
            const int col = nbase + wn + nt * 8 + 2 * tg;
            const float b0 = pb[col], b1 = pb[col + 1];
            float2 o0 = make_float2(acc[mt][nt][0] + b0, acc[mt][nt][1] + b1);
            float2 o1 = make_float2(acc[mt][nt][2] + b0, acc[mt][nt][3] + b1);
            *(float2*)(out + (size_t)row * CDIM + col) = o0;
            *(float2*)(out + (size_t)(row + 8) * CDIM + col) = o1;
        }
    }
}

// ---------------- CPB MLP ----------------
__global__ __launch_bounds__(128) void cpb_kernel(
    const float* __restrict__ table, const float* __restrict__ w1,
    const float* __restrict__ b1, const float* __restrict__ w2) {
    __shared__ float hid[CPBH];
    __shared__ float part[NHEAD][9];
    const int r = blockIdx.x;
    const float t0 = table[r * 2 + 0];
    const float t1 = table[r * 2 + 1];
    for (int j = threadIdx.x; j < CPBH; j += 128)
        hid[j] = fmaxf(w1[j * 2] * t0 + w1[j * 2 + 1] * t1 + b1[j], 0.f);
    __syncthreads();
    const int t = threadIdx.x;
    if (t < 96) {
        const int h = t >> 3, seg = t & 7;
        float s = 0.f;
        const float* wr = w2 + h * CPBH + seg * 64;
        const float* hr = hid + seg * 64;
#pragma unroll 8
        for (int j = 0; j < 64; j++) s += hr[j] * wr[j];
        part[h][seg] = s;
    }
    __syncthreads();
    if (t < NHEAD) {
        float s = 0.f;
#pragma unroll
        for (int seg = 0; seg < 8; seg++) s += part[t][seg];
        g_bt[r * NHEAD + t] = s;
    }
}

__global__ __launch_bounds__(256) void rpb_kernel(const int* __restrict__ rpi) {
    const int h = blockIdx.x >> 8;
    const int i = blockIdx.x & 255;
    const int j = threadIdx.x;
    const int idx = rpi[i * NTOK + j];
    const float v = g_bt[idx * NHEAD + h];
    g_rpb[((size_t)(h * NTOK + i)) * NTOK + j] = LOG2E * 16.f / (1.f + __expf(-v));
}

// ============== bf16-split tensor-core attention (P in registers) ==============
#define KSW 20
#define VSW 132
#define OFF_KLO (256*KSW)
#define OFF_VTHI (2*256*KSW)
#define OFF_VTLO (OFF_VTHI + 32*VSW)
#define OFF_RN  (OFF_VTLO + 32*VSW)
#define ATTN_WORDS (OFF_RN + 256)

__global__ __launch_bounds__(256, 2) void attn_bf16_kernel(const float* __restrict__ lscale) {
    extern __shared__ uint32_t smu[];
    uint32_t* Kh = smu;
    uint32_t* Kl = smu + OFF_KLO;
    uint32_t* Vh = smu + OFF_VTHI;
    uint32_t* Vl = smu + OFF_VTLO;
    float* rn = (float*)(smu + OFF_RN);

    const int b = blockIdx.x / NHEAD;
    const int h = blockIdx.x % NHEAD;
    const int tid = threadIdx.x;
    const int lane = tid & 31;
    const int g = lane >> 2, tg = lane & 3;
    const int wm = (tid >> 5) * 32;

    const size_t base = ((size_t)b * NTOK) * CDIM + h * HDIM;
    const float* gq = g_qkv + base;
    const float* gk = g_qkv + (size_t)MROWS * CDIM + base;
    const float* gv = g_qkv + 2ull * MROWS * CDIM + base;
    const float scale2 = __expf(fminf(lscale[h], 4.60517018598809f)) * LOG2E;

    {
        const int r = tid;
        float tv[32];
        const float* kr = gk + (size_t)r * CDIM;
#pragma unroll
        for (int d = 0; d < HDIM; d += 4) *(float4*)(tv + d) = *(const float4*)(kr + d);
        float ss = 0.f;
#pragma unroll
        for (int d = 0; d < HDIM; d++) ss += tv[d] * tv[d];
        const float rnk = 1.f / fmaxf(sqrtf(ss), 1e-12f);
#pragma unroll
        for (int dw = 0; dw < 16; dw++) {
            uint32_t wh, wl;
            hilo_pack(tv[2 * dw] * rnk, tv[2 * dw + 1] * rnk, wh, wl);
            Kh[r * KSW + dw] = wh;
            Kl[r * KSW + dw] = wl;
        }
        const float* vr = gv + (size_t)r * CDIM;
#pragma unroll
        for (int d = 0; d < HDIM; d += 4) *(float4*)(tv + d) = *(const float4*)(vr + d);
        __nv_bfloat16* Vhb = (__nv_bfloat16*)Vh;
        __nv_bfloat16* Vlb = (__nv_bfloat16*)Vl;
#pragma unroll
        for (int d = 0; d < HDIM; d++) {
            __nv_bfloat16 hi = __float2bfloat16(tv[d]);
            __nv_bfloat16 lo = __float2bfloat16(tv[d] - __bfloat162float(hi));
            Vhb[d * (2 * VSW) + r] = hi;
            Vlb[d * (2 * VSW) + r] = lo;
        }
        const float* qr = gq + (size_t)r * CDIM;
#pragma unroll
        for (int d = 0; d < HDIM; d += 4) *(float4*)(tv + d) = *(const float4*)(qr + d);
        ss = 0.f;
#pragma unroll
        for (int d = 0; d < HDIM; d++) ss += tv[d] * tv[d];
        rn[r] = scale2 / fmaxf(sqrtf(ss), 1e-12f);
    }
    __syncthreads();

    uint32_t qh[2][2][4], ql[2][2][4];
#pragma unroll
    for (int mt = 0; mt < 2; mt++) {
        const int r0 = wm + mt * 16 + g;
        const float n0 = rn[r0], n1 = rn[r0 + 8];
#pragma unroll
        for (int ks = 0; ks < 2; ks++) {
            const int c0 = 16 * ks + 2 * tg;
            float2 a0 = *(const float2*)(gq + (size_t)r0 * CDIM + c0);
            float2 a1 = *(const float2*)(gq + (size_t)(r0 + 8) * CDIM + c0);
            float2 a2 = *(const float2*)(gq + (size_t)r0 * CDIM + c0 + 8);
            float2 a3 = *(const float2*)(gq + (size_t)(r0 + 8) * CDIM + c0 + 8);
            hilo_pack(a0.x * n0, a0.y * n0, qh[mt][ks][0], ql[mt][ks][0]);
            hilo_pack(a1.x * n1, a1.y * n1, qh[mt][ks][1], ql[mt][ks][1]);
            hilo_pack(a2.x * n0, a2.y * n0, qh[mt][ks][2], ql[mt][ks][2]);
            hilo_pack(a3.x * n1, a3.y * n1, qh[mt][ks][3], ql[mt][ks][3]);
        }
    }

    float oa[2][4][4];
    float lsum[2][2];
#pragma unroll
    for (int mt = 0; mt < 2; mt++) {
        lsum[mt][0] = 0.f; lsum[mt][1] = 0.f;
#pragma unroll
        for (int dt = 0; dt < 4; dt++)
#pragma unroll
            for (int i = 0; i < 4; i++) oa[mt][dt][i] = 0.f;
    }

    const float* rpbh = g_rpb + (size_t)h * NTOK * NTOK;

#pragma unroll 1
    for (int jb = 0; jb < 16; jb++) {
        const int j0 = jb * 16;
        float sc[2][2][4];
#pragma unroll
        for (int mt = 0; mt < 2; mt++)
#pragma unroll
            for (int nt = 0; nt < 2; nt++)
#pragma unroll
                for (int i = 0; i < 4; i++) sc[mt][nt][i] = 0.f;

        uint32_t kbh[2][2][2], kbl[2][2][2];
#pragma unroll
        for (int nt = 0; nt < 2; nt++)
#pragma unroll
            for (int ks = 0; ks < 2; ks++) {
                const uint32_t* kp = Kh + (j0 + nt * 8 + g) * KSW + 8 * ks + tg;
                kbh[nt][ks][0] = kp[0];
                kbh[nt][ks][1] = kp[4];
                const uint32_t* kq = Kl + (j0 + nt * 8 + g) * KSW + 8 * ks + tg;
                kbl[nt][ks][0] = kq[0];
                kbl[nt][ks][1] = kq[4];
            }
#pragma unroll
        for (int mt = 0; mt < 2; mt++)
#pragma unroll
            for (int nt = 0; nt < 2; nt++)
#pragma unroll
                for (int ks = 0; ks < 2; ks++) {
                    mma_bf16(sc[mt][nt], qh[mt][ks], kbh[nt][ks]);
                    mma_bf16(sc[mt][nt], qh[mt][ks], kbl[nt][ks]);
                    mma_bf16(sc[mt][nt], ql[mt][ks], kbh[nt][ks]);
                }

        uint32_t pha[2][4], pla[2][4];
#pragma unroll
        for (int mt = 0; mt < 2; mt++) {
            const int row = wm + mt * 16 + g;
#pragma unroll
            for (int nt = 0; nt < 2; nt++) {
                const float2 r0 = *(const float2*)(rpbh + (size_t)row * NTOK + j0 + nt * 8 + 2 * tg);
                const float2 r1 = *(const float2*)(rpbh + (size_t)(row + 8) * NTOK + j0 + nt * 8 + 2 * tg);
                const float p0 = ex2(sc[mt][nt][0] + r0.x);
                const float p1 = ex2(sc[mt][nt][1] + r0.y);
                const float p2 = ex2(sc[mt][nt][2] + r1.x);
                const float p3 = ex2(sc[mt][nt][3] + r1.y);
                lsum[mt][0] += p0 + p1;
                lsum[mt][1] += p2 + p3;
                hilo_pack(p0, p1, pha[mt][2 * nt + 0], pla[mt][2 * nt + 0]);
                hilo_pack(p2, p3, pha[mt][2 * nt + 1], pla[mt][2 * nt + 1]);
            }
        }

        uint32_t vbh[4][2], vbl[4][2];
#pragma unroll
        for (int dt = 0; dt < 4; dt++) {
            const uint32_t* vp = Vh + (dt * 8 + g) * VSW + jb * 8 + tg;
            vbh[dt][0] = vp[0];
            vbh[dt][1] = vp[4];
            const uint32_t* vq = Vl + (dt * 8 + g) * VSW + jb * 8 + tg;
            vbl[dt][0] = vq[0];
            vbl[dt][1] = vq[4];
        }
#pragma unroll
        for (int mt = 0; mt < 2; mt++)
#pragma unroll
            for (int dt = 0; dt < 4; dt++) {
                mma_bf16(oa[mt][dt], pha[mt], vbh[dt]);
                mma_bf16(oa[mt][dt], pla[mt], vbh[dt]);
                mma_bf16(oa[mt][dt], pha[mt], vbl[dt]);
            }
    }

    float inv[2][2];
#pragma unroll
    for (int mt = 0; mt < 2; mt++)
#pragma unroll
        for (int hh = 0; hh < 2; hh++) {
            float s = lsum[mt][hh];
            s += __shfl_xor_sync(0xffffffffu, s, 1);
            s += __shfl_xor_sync(0xffffffffu, s, 2);
            inv[mt][hh] = 1.f / s;
        }
    // store tf32-rounded so proj GEMM operand is pre-converted
#pragma unroll
    for (int mt = 0; mt < 2; mt++) {
        const int row = wm + mt * 16 + g;
#pragma unroll
        for (int dt = 0; dt < 4; dt++) {
            const int col = h * HDIM + dt * 8 + 2 * tg;
            float2 o0 = make_float2(__uint_as_float(f2tf(oa[mt][dt][0] * inv[mt][0])),
                                    __uint_as_float(f2tf(oa[mt][dt][1] * inv[mt][0])));
            float2 o1 = make_float2(__uint_as_float(f2tf(oa[mt][dt][2] * inv[mt][1])),
                                    __uint_as_float(f2tf(oa[mt][dt][3] * inv[mt][1])));
            *(float2*)(g_attout + ((size_t)(b * NTOK + row)) * CDIM + col) = o0;
            *(float2*)(g_attout + ((size_t)(b * NTOK + row + 8)) * CDIM + col) = o1;
        }
    }
}

// ---------------- launch ----------------
extern "C" void kernel_launch(void* const* d_in, const int* in_sizes, int n_in,
                              void* d_out, int out_size) {
    const float* x      = (const float*)d_in[0];
    const float* qkv_w  = (const float*)d_in[1];
    const float* q_bias = (const float*)d_in[2];
    const float* v_bias = (const float*)d_in[3];
    const float* lscale = (const float*)d_in[4];
    const float* cpb_w1 = (const float*)d_in[5];
    const float* cpb_b1 = (const float*)d_in[6];
    const float* cpb_w2 = (const float*)d_in[7];
    const float* proj_w = (const float*)d_in[8];
    const float* proj_b = (const float*)d_in[9];
    const float* table  = (const float*)d_in[10];
    const int*   rpi    = (const int*)d_in[11];
    float* out = (float*)d_out;

    const int attn_smem = ATTN_WORDS * (int)sizeof(uint32_t);
    cudaFuncSetAttribute(attn_bf16_kernel, cudaFuncAttributeMaxDynamicSharedMemorySize,
                         attn_smem);
    cudaFuncSetAttribute(qkv_mma_kernel, cudaFuncAttributeMaxDynamicSharedMemorySize,
                         GEMM_SMEM);
    cudaFuncSetAttribute(proj_mma_kernel, cudaFuncAttributeMaxDynamicSharedMemorySize,
                         GEMM_SMEM);

    float *xt_p, *wt_p, *pwt_p;
    cudaGetSymbolAddress((void**)&xt_p, g_xt);
    cudaGetSymbolAddress((void**)&wt_p, g_wt);
    cudaGetSymbolAddress((void**)&pwt_p, g_pwt);

    // pre-round operands to tf32 (hoists all cvt out of GEMM mainloops)
    cvt_tf32_kernel<<<(MROWS * CDIM / 4 + 255) / 256, 256>>>(x, xt_p, MROWS * CDIM / 4);
    cvt_tf32_kernel<<<(3 * CDIM * CDIM / 4 + 255) / 256, 256>>>(qkv_w, wt_p, 3 * CDIM * CDIM / 4);
    cvt_tf32_kernel<<<(CDIM * CDIM / 4 + 255) / 256, 256>>>(proj_w, pwt_p, CDIM * CDIM / 4);

    qkv_mma_kernel<<<dim3(9, 512), 256, GEMM_SMEM>>>(q_bias, v_bias);
    cpb_kernel<<<TBL, 128>>>(table, cpb_w1, cpb_b1, cpb_w2);
    rpb_kernel<<<NHEAD * NTOK, 256>>>(rpi);
    attn_bf16_kernel<<<BWIN * NHEAD, 256, attn_smem>>>(lscale);
    proj_mma_kernel<<<dim3(3, 512), 256, GEMM_SMEM>>>(proj_b, out);
    (void)in_sizes; (void)n_in; (void)out_size;
}

// round 14
// speedup vs baseline: 1.0776x; 1.0776x over previous
#include <cuda_runtime.h>
#include <cuda_bf16.h>
#include <math.h>
#include <stdint.h>

// Problem constants
#define BWIN 256      // windows*batch
#define NTOK 256      // tokens per window
#define CDIM 384
#define NHEAD 12
#define HDIM 32
#define MROWS (BWIN*NTOK)   // 65536
#define TBL 961             // (2*16-1)^2
#define CPBH 512
#define LOG2E 1.44269504088896f

// ---------------- scratch (device globals; no allocs allowed) ----------------
__device__ float g_qkv[3ull * MROWS * CDIM];     // [3][M][384] f32
__device__ float g_attout[(size_t)MROWS * CDIM]; // [M][384] (tf32-rounded f32)
__device__ float g_xt[(size_t)MROWS * CDIM];     // x pre-rounded to tf32
__device__ float g_wt[3 * CDIM * CDIM];          // qkv_w pre-rounded
__device__ float g_pwt[CDIM * CDIM];             // proj_w pre-rounded
__device__ float g_bt[TBL * NHEAD];
__device__ float g_rpb[(size_t)NHEAD * NTOK * NTOK];

// ---------------- small helpers ----------------
__device__ __forceinline__ uint32_t f2tf(float f) {
    uint32_t u;
    asm("cvt.rna.tf32.f32 %0, %1;" : "=r"(u) : "f"(f));
    return u;
}
__device__ __forceinline__ float ex2(float x) {
    float r;
    asm("ex2.approx.ftz.f32 %0, %1;" : "=f"(r) : "f"(x));
    return r;
}
__device__ __forceinline__ uint32_t smem_u32(const void* p) {
    uint32_t a;
    asm("{ .reg .u64 t; cvta.to.shared.u64 t, %1; cvt.u32.u64 %0, t; }" : "=r"(a) : "l"(p));
    return a;
}
__device__ __forceinline__ void cp16(uint32_t s, const void* g) {
    asm volatile("cp.async.cg.shared.global [%0], [%1], 16;" :: "r"(s), "l"(g) : "memory");
}
__device__ __forceinline__ void ldsm_x4(uint32_t& r0, uint32_t& r1, uint32_t& r2,
                                        uint32_t& r3, uint32_t addr) {
    asm volatile("ldmatrix.sync.aligned.m8n8.x4.shared.b16 {%0,%1,%2,%3}, [%4];"
                 : "=r"(r0), "=r"(r1), "=r"(r2), "=r"(r3) : "r"(addr));
}
__device__ __forceinline__ void mma_tf32(float* c, const uint32_t* a, const uint32_t* b) {
    asm volatile(
        "mma.sync.aligned.m16n8k8.row.col.f32.tf32.tf32.f32 "
        "{%0,%1,%2,%3}, {%4,%5,%6,%7}, {%8,%9}, {%0,%1,%2,%3};\n"
        : "+f"(c[0]), "+f"(c[1]), "+f"(c[2]), "+f"(c[3])
        : "r"(a[0]), "r"(a[1]), "r"(a[2]), "r"(a[3]), "r"(b[0]), "r"(b[1]));
}
__device__ __forceinline__ void mma_bf16(float* c, const uint32_t* a, const uint32_t* b) {
    asm volatile(
        "mma.sync.aligned.m16n8k16.row.col.f32.bf16.bf16.f32 "
        "{%0,%1,%2,%3}, {%4,%5,%6,%7}, {%8,%9}, {%0,%1,%2,%3};\n"
        : "+f"(c[0]), "+f"(c[1]), "+f"(c[2]), "+f"(c[3])
        : "r"(a[0]), "r"(a[1]), "r"(a[2]), "r"(a[3]), "r"(b[0]), "r"(b[1]));
}
__device__ __forceinline__ void hilo_pack(float x, float y, uint32_t& wh, uint32_t& wl) {
    __nv_bfloat16 hx = __float2bfloat16(x);
    __nv_bfloat16 hy = __float2bfloat16(y);
    __nv_bfloat16 lx = __float2bfloat16(x - __bfloat162float(hx));
    __nv_bfloat16 ly = __float2bfloat16(y - __bfloat162float(hy));
    wh = (uint32_t)__bfloat16_as_ushort(hx) | ((uint32_t)__bfloat16_as_ushort(hy) << 16);
    wl = (uint32_t)__bfloat16_as_ushort(lx) | ((uint32_t)__bfloat16_as_ushort(ly) << 16);
}
// truncating hi/lo split via PRMT (lo term absorbs the truncation; net err < 2^-16)
__device__ __forceinline__ void hilo_pack_trunc(float x, float y, uint32_t& wh, uint32_t& wl) {
    const uint32_t xb = __float_as_uint(x), yb = __float_as_uint(y);
    asm("prmt.b32 %0, %1, %2, 0x7632;" : "=r"(wh) : "r"(xb), "r"(yb));
    const float xl = x - __uint_as_float(xb & 0xFFFF0000u);
    const float yl = y - __uint_as_float(yb & 0xFFFF0000u);
    asm("prmt.b32 %0, %1, %2, 0x7632;" : "=r"(wl)
        : "r"(__float_as_uint(xl)), "r"(__float_as_uint(yl)));
}

// ---------------- conversion kernel: round f32 -> tf32 bit pattern ----------------
__global__ __launch_bounds__(256) void cvt_tf32_kernel(const float* __restrict__ in,
                                                       float* __restrict__ out, int n4) {
    int i = blockIdx.x * 256 + threadIdx.x;
    if (i >= n4) return;
    float4 v = ((const float4*)in)[i];
    v.x = __uint_as_float(f2tf(v.x));
    v.y = __uint_as_float(f2tf(v.y));
    v.z = __uint_as_float(f2tf(v.z));
    v.w = __uint_as_float(f2tf(v.w));
    ((float4*)out)[i] = v;
}

// ==================== tf32 mma.sync GEMM (R10 config: K-chunk 16, 5-stage) ====================
#define NSTG 5
#define STW 20
#define STG_A_WORDS (128 * STW)            // 2560 words
#define STG_BYTES (2 * STG_A_WORDS * 4)    // 20480 B (A + B)
#define GEMM_SMEM (NSTG * STG_BYTES)       // 102400 B
#define NCHUNK (CDIM / 16)                 // 24

#define CP_CHUNK(c_) do { \
    const int b_ = (c_) % NSTG; \
    const uint32_t ab_ = sb + b_ * STG_BYTES; \
    const uint32_t bb_ = ab_ + STG_A_WORDS * 4; \
    const float* ga_ = Ag + (size_t)lrow * CDIM + (c_) * 16 + half * 8; \
    const float* gb_ = Bg + (size_t)lrow * CDIM + (c_) * 16 + half * 8; \
    const uint32_t so_ = lrow * (STW * 4) + half * 32; \
    cp16(ab_ + so_, ga_); \
    cp16(ab_ + so_ + 16, ga_ + 4); \
    cp16(bb_ + so_, gb_); \
    cp16(bb_ + so_ + 16, gb_ + 4); \
    asm volatile("cp.async.commit_group;" ::: "memory"); \
} while (0)

__device__ __forceinline__ void mma_gemm_core(
    const float* __restrict__ Ag, const float* __restrict__ Bg,
    float acc[4][4][4], char* smem) {
    const uint32_t sb = smem_u32(smem);
    const int tid = threadIdx.x;
    const int lane = tid & 31;
    const int wm = ((tid >> 5) >> 2) * 64;   // warp m offset (0,64)
    const int wn = ((tid >> 5) & 3) * 32;    // warp n offset (0..96)
    const int lrow = tid >> 1;               // 0..127
    const int half = tid & 1;                // 0..1

    const int arow = (lane & 7) + (lane & 8);
    const int acol = (lane & 16) ? 4 : 0;
    const uint32_t aoffw = (uint32_t)((wm + arow) * STW + acol);
    const int brow = (lane & 7) + ((lane & 16) ? 8 : 0);
    const int bcol = (lane & 8) ? 4 : 0;
    const uint32_t boffw = (uint32_t)((wn + brow) * STW + bcol);

    CP_CHUNK(0); CP_CHUNK(1); CP_CHUNK(2);

#pragma unroll 1
    for (int c = 0; c < NCHUNK; c++) {
        if (c + 3 < NCHUNK) {
            CP_CHUNK(c + 3);
        } else {
            asm volatile("cp.async.commit_group;" ::: "memory");
        }
        asm volatile("cp.async.wait_group 3;" ::: "memory");
        __syncthreads();

        const uint32_t abase = sb + (c % NSTG) * STG_BYTES;
        const uint32_t bbase = abase + STG_A_WORDS * 4;
#pragma unroll
        for (int ks = 0; ks < 2; ks++) {
            uint32_t a[4][4], b[2][4];
#pragma unroll
            for (int mt = 0; mt < 4; mt++)
                ldsm_x4(a[mt][0], a[mt][1], a[mt][2], a[mt][3],
                        abase + ((aoffw + (uint32_t)(mt * 16 * STW + ks * 8)) << 2));
#pragma unroll
            for (int pr = 0; pr < 2; pr++)
                ldsm_x4(b[pr][0], b[pr][1], b[pr][2], b[pr][3],
                        bbase + ((boffw + (uint32_t)(pr * 16 * STW + ks * 8)) << 2));
#pragma unroll
            for (int mt = 0; mt < 4; mt++)
#pragma unroll
                for (int nt = 0; nt < 4; nt++)
                    mma_tf32(acc[mt][nt], a[mt], &b[nt >> 1][(nt & 1) * 2]);
        }
    }
}

// QKV: A=g_xt, B=g_wt, out -> g_qkv (+ q/v bias)
__global__ __launch_bounds__(256, 2) void qkv_mma_kernel(
    const float* __restrict__ qb, const float* __restrict__ vb) {
    extern __shared__ char smem[];
    float acc[4][4][4];
#pragma unroll
    for (int i = 0; i < 4; i++)
#pragma unroll
        for (int j = 0; j < 4; j++)
#pragma unroll
            for (int k = 0; k < 4; k++) acc[i][j][k] = 0.f;

    const float* Ag = g_xt + (size_t)blockIdx.y * 128 * CDIM;
    const float* Bg = g_wt + (size_t)blockIdx.x * 128 * CDIM;
    mma_gemm_core(Ag, Bg, acc, smem);

    const int tid = threadIdx.x;
    const int lane = tid & 31;
    const int wm = ((tid >> 5) >> 2) * 64;
    const int wn = ((tid >> 5) & 3) * 32;
    const int g = lane >> 2, tg = lane & 3;

    const int nbase = blockIdx.x * 128;
    const int which = nbase / CDIM;
    const int cb = nbase % CDIM;
    float* outp = g_qkv + (size_t)which * MROWS * CDIM;

#pragma unroll
    for (int mt = 0; mt < 4; mt++) {
        const int row = blockIdx.y * 128 + wm + mt * 16 + g;
#pragma unroll
        for (int nt = 0; nt < 4; nt++) {
            const int col = cb + wn + nt * 8 + 2 * tg;
            float b0 = 0.f, b1 = 0.f;
            if (which == 0) { b0 = qb[col]; b1 = qb[col + 1]; }
            else if (which == 2) { b0 = vb[col]; b1 = vb[col + 1]; }
            float2 o0 = make_float2(acc[mt][nt][0] + b0, acc[mt][nt][1] + b1);
            float2 o1 = make_float2(acc[mt][nt][2] + b0, acc[mt][nt][3] + b1);
            *(float2*)(outp + (size_t)row * CDIM + col) = o0;
            *(float2*)(outp + (size_t)(row + 8) * CDIM + col) = o1;
        }
    }
}

// Proj: A=g_attout (tf32-rounded by attention), B=g_pwt, out -> d_out (+ bias)
__global__ __launch_bounds__(256, 2) void proj_mma_kernel(
    const float* __restrict__ pb, float* __restrict__ out) {
    extern __shared__ char smem[];
    float acc[4][4][4];
#pragma unroll
    for (int i = 0; i < 4; i++)
#pragma unroll
        for (int j = 0; j < 4; j++)
#pragma unroll
            for (int k = 0; k < 4; k++) acc[i][j][k] = 0.f;

    const float* Ag = g_attout + (size_t)blockIdx.y * 128 * CDIM;
    const float* Bg = g_pwt + (size_t)blockIdx.x * 128 * CDIM;
    mma_gemm_core(Ag, Bg, acc, smem);

    const int tid = threadIdx.x;
    const int lane = tid & 31;
    const int wm = ((tid >> 5) >> 2) * 64;
    const int wn = ((tid >> 5) & 3) * 32;
    const int g = lane >> 2, tg = lane & 3;
    const int nbase = blockIdx.x * 128;

#pragma unroll
    for (int mt = 0; mt < 4; mt++) {
        const int row = blockIdx.y * 128 + wm + mt * 16 + g;
#pragma unroll
        for (int nt = 0; nt < 4; nt++) {
            const int col = nbase + wn + nt * 8 + 2 * tg;
            const float b0 = pb[col], b1 = pb[col + 1];
            float2 o0 = make_float2(acc[mt][nt][0] + b0, acc[mt][nt][1] + b1);
            float2 o1 = make_float2(acc[mt][nt][2] + b0, acc[mt][nt][3] + b1);
            *(float2*)(out + (size_t)row * CDIM + col) = o0;
            *(float2*)(out + (size_t)(row + 8) * CDIM + col) = o1;
        }
    }
}

// ---------------- CPB MLP ----------------
__global__ __launch_bounds__(128) void cpb_kernel(
    const float* __restrict__ table, const float* __restrict__ w1,
    const float* __restrict__ b1, const float* __restrict__ w2) {
    __shared__ float hid[CPBH];
    __shared__ float part[NHEAD][9];
    const int r = blockIdx.x;
    const float t0 = table[r * 2 + 0];
    const float t1 = table[r * 2 + 1];
    for (int j = threadIdx.x; j < CPBH; j += 128)
        hid[j] = fmaxf(w1[j * 2] * t0 + w1[j * 2 + 1] * t1 + b1[j], 0.f);
    __syncthreads();
    const int t = threadIdx.x;
    if (t < 96) {
        const int h = t >> 3, seg = t & 7;
        float s = 0.f;
        const float* wr = w2 + h * CPBH + seg * 64;
        const float* hr = hid + seg * 64;
#pragma unroll 8
        for (int j = 0; j < 64; j++) s += hr[j] * wr[j];
        part[h][seg] = s;
    }
    __syncthreads();
    if (t < NHEAD) {
        float s = 0.f;
#pragma unroll
        for (int seg = 0; seg < 8; seg++) s += part[t][seg];
        g_bt[r * NHEAD + t] = s;
    }
}

__global__ __launch_bounds__(256) void rpb_kernel(const int* __restrict__ rpi) {
    const int h = blockIdx.x >> 8;
    const int i = blockIdx.x & 255;
    const int j = threadIdx.x;
    const int idx = rpi[i * NTOK + j];
    const float v = g_bt[idx * NHEAD + h];
    g_rpb[((size_t)(h * NTOK + i)) * NTOK + j] = LOG2E * 16.f / (1.f + __expf(-v));
}

// ============== bf16-split tensor-core attention (P in regs, ldmatrix K/V) ==============
#define KSW 20
#define VSW 132
#define OFF_KLO (256*KSW)
#define OFF_VTHI (2*256*KSW)
#define OFF_VTLO (OFF_VTHI + 32*VSW)
#define OFF_RN  (OFF_VTLO + 32*VSW)
#define ATTN_WORDS (OFF_RN + 256)

__global__ __launch_bounds__(256, 2) void attn_bf16_kernel(const float* __restrict__ lscale) {
    extern __shared__ uint32_t smu[];
    uint32_t* Kh = smu;
    uint32_t* Kl = smu + OFF_KLO;
    uint32_t* Vh = smu + OFF_VTHI;
    uint32_t* Vl = smu + OFF_VTLO;
    float* rn = (float*)(smu + OFF_RN);
    const uint32_t sbase = smem_u32(smu);
    const uint32_t kh_b = sbase;
    const uint32_t kl_b = sbase + OFF_KLO * 4;
    const uint32_t vh_b = sbase + OFF_VTHI * 4;
    const uint32_t vl_b = sbase + OFF_VTLO * 4;

    const int b = blockIdx.x / NHEAD;
    const int h = blockIdx.x % NHEAD;
    const int tid = threadIdx.x;
    const int lane = tid & 31;
    const int g = lane >> 2, tg = lane & 3;
    const int wm = (tid >> 5) * 32;

    const size_t base = ((size_t)b * NTOK) * CDIM + h * HDIM;
    const float* gq = g_qkv + base;
    const float* gk = g_qkv + (size_t)MROWS * CDIM + base;
    const float* gv = g_qkv + 2ull * MROWS * CDIM + base;
    const float scale2 = __expf(fminf(lscale[h], 4.60517018598809f)) * LOG2E;

    // ---- load phase: thread r handles row r of k, v, q ----
    {
        const int r = tid;
        float tv[32];
        const float* kr = gk + (size_t)r * CDIM;
#pragma unroll
        for (int d = 0; d < HDIM; d += 4) *(float4*)(tv + d) = *(const float4*)(kr + d);
        float ss = 0.f;
#pragma unroll
        for (int d = 0; d < HDIM; d++) ss += tv[d] * tv[d];
        const float rnk = 1.f / fmaxf(sqrtf(ss), 1e-12f);
#pragma unroll
        for (int dw = 0; dw < 16; dw++) {
            uint32_t wh, wl;
            hilo_pack(tv[2 * dw] * rnk, tv[2 * dw + 1] * rnk, wh, wl);
            Kh[r * KSW + dw] = wh;
            Kl[r * KSW + dw] = wl;
        }
        const float* vr = gv + (size_t)r * CDIM;
#pragma unroll
        for (int d = 0; d < HDIM; d += 4) *(float4*)(tv + d) = *(const float4*)(vr + d);
        __nv_bfloat16* Vhb = (__nv_bfloat16*)Vh;
        __nv_bfloat16* Vlb = (__nv_bfloat16*)Vl;
#pragma unroll
        for (int d = 0; d < HDIM; d++) {
            __nv_bfloat16 hi = __float2bfloat16(tv[d]);
            __nv_bfloat16 lo = __float2bfloat16(tv[d] - __bfloat162float(hi));
            Vhb[d * (2 * VSW) + r] = hi;
            Vlb[d * (2 * VSW) + r] = lo;
        }
        const float* qr = gq + (size_t)r * CDIM;
#pragma unroll
        for (int d = 0; d < HDIM; d += 4) *(float4*)(tv + d) = *(const float4*)(qr + d);
        ss = 0.f;
#pragma unroll
        for (int d = 0; d < HDIM; d++) ss += tv[d] * tv[d];
        rn[r] = scale2 / fmaxf(sqrtf(ss), 1e-12f);
    }
    __syncthreads();

    // ---- q A-fragments (hi/lo), from gmem, kept in regs ----
    uint32_t qh[2][2][4], ql[2][2][4];
#pragma unroll
    for (int mt = 0; mt < 2; mt++) {
        const int r0 = wm + mt * 16 + g;
        const float n0 = rn[r0], n1 = rn[r0 + 8];
#pragma unroll
        for (int ks = 0; ks < 2; ks++) {
            const int c0 = 16 * ks + 2 * tg;
            float2 a0 = *(const float2*)(gq + (size_t)r0 * CDIM + c0);
            float2 a1 = *(const float2*)(gq + (size_t)(r0 + 8) * CDIM + c0);
            float2 a2 = *(const float2*)(gq + (size_t)r0 * CDIM + c0 + 8);
            float2 a3 = *(const float2*)(gq + (size_t)(r0 + 8) * CDIM + c0 + 8);
            hilo_pack(a0.x * n0, a0.y * n0, qh[mt][ks][0], ql[mt][ks][0]);
            hilo_pack(a1.x * n1, a1.y * n1, qh[mt][ks][1], ql[mt][ks][1]);
            hilo_pack(a2.x * n0, a2.y * n0, qh[mt][ks][2], ql[mt][ks][2]);
            hilo_pack(a3.x * n1, a3.y * n1, qh[mt][ks][3], ql[mt][ks][3]);
        }
    }

    float oa[2][4][4];
    float lsum[2][2];
#pragma unroll
    for (int mt = 0; mt < 2; mt++) {
        lsum[mt][0] = 0.f; lsum[mt][1] = 0.f;
#pragma unroll
        for (int dt = 0; dt < 4; dt++)
#pragma unroll
            for (int i = 0; i < 4; i++) oa[mt][dt][i] = 0.f;
    }

    const float* rpbh = g_rpb + (size_t)h * NTOK * NTOK;

    // per-lane ldmatrix address components
    const int lr8 = lane & 7;
    const int lq4 = (lane >> 3) * 4;                     // K: word offset 0,4,8,12
    const int vrow = (lane & 7) + ((lane & 16) ? 8 : 0); // V: row within dt-pair
    const int vcol = (lane & 8) ? 4 : 0;                 // V: word offset

#pragma unroll 1
    for (int jb = 0; jb < 16; jb++) {
        const int j0 = jb * 16;
        float sc[2][2][4];
#pragma unroll
        for (int mt = 0; mt < 2; mt++)
#pragma unroll
            for (int nt = 0; nt < 2; nt++)
#pragma unroll
                for (int i = 0; i < 4; i++) sc[mt][nt][i] = 0.f;

        // ---- K fragments via ldmatrix.x4: regs {ks0b0, ks0b1, ks1b0, ks1b1} ----
        uint32_t kbh[2][4], kbl[2][4];
#pragma unroll
        for (int nt = 0; nt < 2; nt++) {
            const uint32_t koff = (uint32_t)(((j0 + nt * 8 + lr8) * KSW + lq4) << 2);
            ldsm_x4(kbh[nt][0], kbh[nt][1], kbh[nt][2], kbh[nt][3], kh_b + koff);
            ldsm_x4(kbl[nt][0], kbl[nt][1], kbl[nt][2], kbl[nt][3], kl_b + koff);
        }
#pragma unroll
        for (int mt = 0; mt < 2; mt++)
#pragma unroll
            for (int nt = 0; nt < 2; nt++)
#pragma unroll
                for (int ks = 0; ks < 2; ks++) {
                    mma_bf16(sc[mt][nt], qh[mt][ks], &kbh[nt][2 * ks]);
                    mma_bf16(sc[mt][nt], qh[mt][ks], &kbl[nt][2 * ks]);
                    mma_bf16(sc[mt][nt], ql[mt][ks], &kbh[nt][2 * ks]);
                }

        // ---- + rpb, exp2, l accumulation, pack P hi/lo (prmt trunc split) ----
        uint32_t pha[2][4], pla[2][4];
#pragma unroll
        for (int mt = 0; mt < 2; mt++) {
            const int row = wm + mt * 16 + g;
#pragma unroll
            for (int nt = 0; nt < 2; nt++) {
                const float2 r0 = *(const float2*)(rpbh + (size_t)row * NTOK + j0 + nt * 8 + 2 * tg);
                const float2 r1 = *(const float2*)(rpbh + (size_t)(row + 8) * NTOK + j0 + nt * 8 + 2 * tg);
                const float p0 = ex2(sc[mt][nt][0] + r0.x);
                const float p1 = ex2(sc[mt][nt][1] + r0.y);
                const float p2 = ex2(sc[mt][nt][2] + r1.x);
                const float p3 = ex2(sc[mt][nt][3] + r1.y);
                lsum[mt][0] += p0 + p1;
                lsum[mt][1] += p2 + p3;
                hilo_pack_trunc(p0, p1, pha[mt][2 * nt + 0], pla[mt][2 * nt + 0]);
                hilo_pack_trunc(p2, p3, pha[mt][2 * nt + 1], pla[mt][2 * nt + 1]);
            }
        }

        // ---- V fragments via ldmatrix.x4: regs {dt0b0, dt0b1, dt1b0, dt1b1} ----
        uint32_t vbh[2][4], vbl[2][4];
#pragma unroll
        for (int dp = 0; dp < 2; dp++) {
            const uint32_t voff = (uint32_t)(((dp * 16 + vrow) * VSW + jb * 8 + vcol) << 2);
            ldsm_x4(vbh[dp][0], vbh[dp][1], vbh[dp][2], vbh[dp][3], vh_b + voff);
            ldsm_x4(vbl[dp][0], vbl[dp][1], vbl[dp][2], vbl[dp][3], vl_b + voff);
        }
#pragma unroll
        for (int mt = 0; mt < 2; mt++)
#pragma unroll
            for (int dt = 0; dt < 4; dt++) {
                mma_bf16(oa[mt][dt], pha[mt], &vbh[dt >> 1][(dt & 1) * 2]);
                mma_bf16(oa[mt][dt], pla[mt], &vbh[dt >> 1][(dt & 1) * 2]);
                mma_bf16(oa[mt][dt], pha[mt], &vbl[dt >> 1][(dt & 1) * 2]);
            }
    }

    float inv[2][2];
#pragma unroll
    for (int mt = 0; mt < 2; mt++)
#pragma unroll
        for (int hh = 0; hh < 2; hh++) {
            float s = lsum[mt][hh];
            s += __shfl_xor_sync(0xffffffffu, s, 1);
            s += __shfl_xor_sync(0xffffffffu, s, 2);
            inv[mt][hh] = 1.f / s;
        }
    // store tf32-rounded so proj GEMM operand is pre-converted
#pragma unroll
    for (int mt = 0; mt < 2; mt++) {
        const int row = wm + mt * 16 + g;
#pragma unroll
        for (int dt = 0; dt < 4; dt++) {
            const int col = h * HDIM + dt * 8 + 2 * tg;
            float2 o0 = make_float2(__uint_as_float(f2tf(oa[mt][dt][0] * inv[mt][0])),
                                    __uint_as_float(f2tf(oa[mt][dt][1] * inv[mt][0])));
            float2 o1 = make_float2(__uint_as_float(f2tf(oa[mt][dt][2] * inv[mt][1])),
                                    __uint_as_float(f2tf(oa[mt][dt][3] * inv[mt][1])));
            *(float2*)(g_attout + ((size_t)(b * NTOK + row)) * CDIM + col) = o0;
            *(float2*)(g_attout + ((size_t)(b * NTOK + row + 8)) * CDIM + col) = o1;
        }
    }
}

// ---------------- launch ----------------
extern "C" void kernel_launch(void* const* d_in, const int* in_sizes, int n_in,
                              void* d_out, int out_size) {
    const float* x      = (const float*)d_in[0];
    const float* qkv_w  = (const float*)d_in[1];
    const float* q_bias = (const float*)d_in[2];
    const float* v_bias = (const float*)d_in[3];
    const float* lscale = (const float*)d_in[4];
    const float* cpb_w1 = (const float*)d_in[5];
    const float* cpb_b1 = (const float*)d_in[6];
    const float* cpb_w2 = (const float*)d_in[7];
    const float* proj_w = (const float*)d_in[8];
    const float* proj_b = (const float*)d_in[9];
    const float* table  = (const float*)d_in[10];
    const int*   rpi    = (const int*)d_in[11];
    float* out = (float*)d_out;

    const int attn_smem = ATTN_WORDS * (int)sizeof(uint32_t);
    cudaFuncSetAttribute(attn_bf16_kernel, cudaFuncAttributeMaxDynamicSharedMemorySize,
                         attn_smem);
    cudaFuncSetAttribute(qkv_mma_kernel, cudaFuncAttributeMaxDynamicSharedMemorySize,
                         GEMM_SMEM);
    cudaFuncSetAttribute(proj_mma_kernel, cudaFuncAttributeMaxDynamicSharedMemorySize,
                         GEMM_SMEM);

    float *xt_p, *wt_p, *pwt_p;
    cudaGetSymbolAddress((void**)&xt_p, g_xt);
    cudaGetSymbolAddress((void**)&wt_p, g_wt);
    cudaGetSymbolAddress((void**)&pwt_p, g_pwt);

    // pre-round operands to tf32 (hoists all cvt out of GEMM mainloops)
    cvt_tf32_kernel<<<(MROWS * CDIM / 4 + 255) / 256, 256>>>(x, xt_p, MROWS * CDIM / 4);
    cvt_tf32_kernel<<<(3 * CDIM * CDIM / 4 + 255) / 256, 256>>>(qkv_w, wt_p, 3 * CDIM * CDIM / 4);
    cvt_tf32_kernel<<<(CDIM * CDIM / 4 + 255) / 256, 256>>>(proj_w, pwt_p, CDIM * CDIM / 4);

    qkv_mma_kernel<<<dim3(9, 512), 256, GEMM_SMEM>>>(q_bias, v_bias);
    cpb_kernel<<<TBL, 128>>>(table, cpb_w1, cpb_b1, cpb_w2);
    rpb_kernel<<<NHEAD * NTOK, 256>>>(rpi);
    attn_bf16_kernel<<<BWIN * NHEAD, 256, attn_smem>>>(lscale);
    proj_mma_kernel<<<dim3(3, 512), 256, GEMM_SMEM>>>(proj_b, out);
    (void)in_sizes; (void)n_in; (void)out_size;
}